// round 1
// baseline (speedup 1.0000x reference)
#include <cuda_runtime.h>
#include <cuda_bf16.h>

// Problem constants (fixed by the dataset)
#define B    256
#define G    20000
#define NTF  1024
#define NPT  8     // nodes per TF
#define GPT  64    // genes per TF
#define EPS  1e-5f
#define SLOPE 0.01f

// Scratch: x transposed to [G, B] for coalesced gene-row gathers. 20.48 MB.
__device__ float g_xT[(size_t)G * B];

// ---------------------------------------------------------------------------
// Kernel 1: transpose x [B, G] -> xT [G, B].  G = 625 * 32 exactly.
// ---------------------------------------------------------------------------
__global__ void __launch_bounds__(256) transpose_kernel(const float* __restrict__ x) {
    __shared__ float tile[32][33];
    const int g0 = blockIdx.x * 32;
    const int b0 = blockIdx.y * 32;
    const int tx = threadIdx.x;      // 0..31
    const int ty = threadIdx.y;      // 0..7

#pragma unroll
    for (int i = 0; i < 32; i += 8) {
        // coalesced read along G
        tile[ty + i][tx] = x[(size_t)(b0 + ty + i) * G + (g0 + tx)];
    }
    __syncthreads();
#pragma unroll
    for (int i = 0; i < 32; i += 8) {
        // coalesced write along B
        g_xT[(size_t)(g0 + ty + i) * B + (b0 + tx)] = tile[tx][ty + i];
    }
}

// ---------------------------------------------------------------------------
// Kernel 2: fully fused per-TF block:
//   layer1 (64-gene x 8-node dense block) -> BN1 -> LeakyReLU
//   -> layer2 (8-node dot) -> BN2 -> LeakyReLU -> out
// Block t handles TF t; thread = batch index b (256 threads).
// ---------------------------------------------------------------------------
__global__ void __launch_bounds__(256) fused_encoder_kernel(
    const float* __restrict__ w1,
    const int*   __restrict__ in_idx1,
    const float* __restrict__ w2,
    float*       __restrict__ out)
{
    const int t    = blockIdx.x;
    const int tid  = threadIdx.x;     // = batch index b
    const int wid  = tid >> 5;
    const int lane = tid & 31;

    __shared__ float sw1[NPT * GPT];     // 512 weights of this TF
    __shared__ int   sg[GPT];            // 64 gene base offsets (pre-scaled by B)
    __shared__ float sw2[NPT];
    __shared__ float rsum[8][9];         // per-warp partials (padded)
    __shared__ float rsq[8][9];
    __shared__ float smean[NPT], srstd[NPT];
    __shared__ float zmean, zrstd;

    // Stage weights + indices. w1 slice for TF t: [t*512, t*512+512).
    sw1[tid]       = w1[t * (NPT * GPT) + tid];
    sw1[tid + 256] = w1[t * (NPT * GPT) + tid + 256];
    if (tid < GPT) sg[tid]  = in_idx1[t * (NPT * GPT) + tid] * B;  // node 0's genes == all nodes' genes
    if (tid < NPT) sw2[tid] = w2[t * NPT + tid];
    __syncthreads();

    // ---- Layer 1: acc[j] = sum_g w1[j*64+g] * xT[gene_g][b] -----------------
    float acc[NPT];
#pragma unroll
    for (int j = 0; j < NPT; j++) acc[j] = 0.f;

#pragma unroll 8
    for (int g = 0; g < GPT; g++) {
        const float v = g_xT[sg[g] + tid];          // coalesced across threads
#pragma unroll
        for (int j = 0; j < NPT; j++)
            acc[j] = fmaf(sw1[j * GPT + g], v, acc[j]);
    }

    // ---- BN1 stats: mean/var over batch (256 threads) per node j ------------
#pragma unroll
    for (int j = 0; j < NPT; j++) {
        float s  = acc[j];
        float s2 = acc[j] * acc[j];
#pragma unroll
        for (int o = 16; o > 0; o >>= 1) {
            s  += __shfl_xor_sync(0xffffffffu, s,  o);
            s2 += __shfl_xor_sync(0xffffffffu, s2, o);
        }
        if (lane == 0) { rsum[wid][j] = s; rsq[wid][j] = s2; }
    }
    __syncthreads();
    if (tid < NPT) {
        float s = 0.f, s2 = 0.f;
#pragma unroll
        for (int w = 0; w < 8; w++) { s += rsum[w][tid]; s2 += rsq[w][tid]; }
        const float m   = s * (1.f / B);
        const float var = s2 * (1.f / B) - m * m;
        smean[tid] = m;
        srstd[tid] = rsqrtf(var + EPS);
    }
    __syncthreads();

    // ---- BN1 + LeakyReLU + Layer 2 dot --------------------------------------
    float z = 0.f;
#pragma unroll
    for (int j = 0; j < NPT; j++) {
        float v = (acc[j] - smean[j]) * srstd[j];
        v = (v > 0.f) ? v : SLOPE * v;
        z = fmaf(sw2[j], v, z);
    }

    // ---- BN2 stats over the 256 batch values held one-per-thread ------------
    {
        float s = z, s2 = z * z;
#pragma unroll
        for (int o = 16; o > 0; o >>= 1) {
            s  += __shfl_xor_sync(0xffffffffu, s,  o);
            s2 += __shfl_xor_sync(0xffffffffu, s2, o);
        }
        if (lane == 0) { rsum[wid][8] = s; rsq[wid][8] = s2; }
    }
    __syncthreads();
    if (tid == 0) {
        float s = 0.f, s2 = 0.f;
#pragma unroll
        for (int w = 0; w < 8; w++) { s += rsum[w][8]; s2 += rsq[w][8]; }
        const float m   = s * (1.f / B);
        const float var = s2 * (1.f / B) - m * m;
        zmean = m;
        zrstd = rsqrtf(var + EPS);
    }
    __syncthreads();

    float v = (z - zmean) * zrstd;
    v = (v > 0.f) ? v : SLOPE * v;
    out[(size_t)tid * NTF + t] = v;   // out[b, t]
}

// ---------------------------------------------------------------------------
extern "C" void kernel_launch(void* const* d_in, const int* in_sizes, int n_in,
                              void* d_out, int out_size) {
    const float* x       = (const float*)d_in[0];
    const float* w1      = (const float*)d_in[1];
    const int*   in_idx1 = (const int*)  d_in[2];
    // d_in[3] = out_idx1 (implied by layout), d_in[5..6] identity — unused
    const float* w2      = (const float*)d_in[4];
    float*       out     = (float*)d_out;

    dim3 tb(32, 8);
    dim3 tg(G / 32, B / 32);           // 625 x 8, exact
    transpose_kernel<<<tg, tb>>>(x);
    fused_encoder_kernel<<<NTF, 256>>>(w1, in_idx1, w2, out);
}

// round 2
// speedup vs baseline: 1.1764x; 1.1764x over previous
#include <cuda_runtime.h>
#include <cuda_bf16.h>

// Problem constants (fixed by the dataset)
#define B    256
#define G    20000
#define NTF  1024
#define NPT  8     // nodes per TF
#define GPT  64    // genes per TF
#define EPS  1e-5f
#define SLOPE 0.01f

// Scratch: x transposed to [G, B] for coalesced gene-row gathers. 20.48 MB.
__device__ float g_xT[(size_t)G * B];

// ---------------------------------------------------------------------------
// Kernel 1: transpose x [B, G] -> xT [G, B].  G = 625 * 32 exactly.
// ---------------------------------------------------------------------------
__global__ void __launch_bounds__(256) transpose_kernel(const float* __restrict__ x) {
    __shared__ float tile[32][33];
    const int g0 = blockIdx.x * 32;
    const int b0 = blockIdx.y * 32;
    const int tx = threadIdx.x;      // 0..31
    const int ty = threadIdx.y;      // 0..7

#pragma unroll
    for (int i = 0; i < 32; i += 8)
        tile[ty + i][tx] = x[(size_t)(b0 + ty + i) * G + (g0 + tx)];
    __syncthreads();
#pragma unroll
    for (int i = 0; i < 32; i += 8)
        g_xT[(size_t)(g0 + ty + i) * B + (b0 + tx)] = tile[tx][ty + i];
}

// ---------------------------------------------------------------------------
// Kernel 2: fused encoder, 2 TFs per block.
//   Half-block h (128 threads) handles TF t = 2*blockIdx.x + h.
//   Each thread handles 2 batch elements (2*htid, 2*htid+1) via float2.
//   layer1 -> BN1 -> LeakyReLU -> layer2 -> BN2 -> LeakyReLU -> out.
// ---------------------------------------------------------------------------
__global__ void __launch_bounds__(256) fused_encoder_kernel(
    const float* __restrict__ w1,
    const int*   __restrict__ in_idx1,
    const float* __restrict__ w2,
    float*       __restrict__ out)
{
    const int tid  = threadIdx.x;
    const int half = tid >> 7;        // 0 or 1
    const int htid = tid & 127;       // thread within half
    const int hw   = htid >> 5;       // warp within half: 0..3
    const int lane = tid & 31;
    const int t    = blockIdx.x * 2 + half;

    __shared__ float sw1t[2][NPT * GPT];   // transposed: [g*8 + j]
    __shared__ int   sg[2][GPT];           // gene offsets pre-scaled by B
    __shared__ float sw2[2][NPT];
    __shared__ float rsum[2][4][NPT + 2];  // per-half, per-warp partials ([8]=z)
    __shared__ float rsq [2][4][NPT + 2];
    __shared__ float smean[2][NPT], srstd[2][NPT];
    __shared__ float zmean[2], zrstd[2];

    // ---- Stage weights (transposed) + gene indices per half ------------------
#pragma unroll
    for (int i = htid; i < NPT * GPT; i += 128) {
        const int j = i >> 6;          // node
        const int g = i & 63;          // gene slot
        sw1t[half][g * NPT + j] = w1[t * (NPT * GPT) + i];
    }
    if (htid < GPT) sg[half][htid]  = in_idx1[t * (NPT * GPT) + htid] * B;
    if (htid < NPT) sw2[half][htid] = w2[t * NPT + htid];
    __syncthreads();

    // ---- Layer 1: acc[j] (float2 over 2 batch elems) -------------------------
    float2 acc[NPT];
#pragma unroll
    for (int j = 0; j < NPT; j++) acc[j] = make_float2(0.f, 0.f);

    const int boff = 2 * htid;
#pragma unroll
    for (int g0 = 0; g0 < GPT; g0 += 4) {
        float2 xv[4];
#pragma unroll
        for (int u = 0; u < 4; u++)
            xv[u] = *(const float2*)&g_xT[sg[half][g0 + u] + boff];
#pragma unroll
        for (int u = 0; u < 4; u++) {
            const float4 wa = *(const float4*)&sw1t[half][(g0 + u) * NPT];
            const float4 wb = *(const float4*)&sw1t[half][(g0 + u) * NPT + 4];
            acc[0].x = fmaf(wa.x, xv[u].x, acc[0].x); acc[0].y = fmaf(wa.x, xv[u].y, acc[0].y);
            acc[1].x = fmaf(wa.y, xv[u].x, acc[1].x); acc[1].y = fmaf(wa.y, xv[u].y, acc[1].y);
            acc[2].x = fmaf(wa.z, xv[u].x, acc[2].x); acc[2].y = fmaf(wa.z, xv[u].y, acc[2].y);
            acc[3].x = fmaf(wa.w, xv[u].x, acc[3].x); acc[3].y = fmaf(wa.w, xv[u].y, acc[3].y);
            acc[4].x = fmaf(wb.x, xv[u].x, acc[4].x); acc[4].y = fmaf(wb.x, xv[u].y, acc[4].y);
            acc[5].x = fmaf(wb.y, xv[u].x, acc[5].x); acc[5].y = fmaf(wb.y, xv[u].y, acc[5].y);
            acc[6].x = fmaf(wb.z, xv[u].x, acc[6].x); acc[6].y = fmaf(wb.z, xv[u].y, acc[6].y);
            acc[7].x = fmaf(wb.w, xv[u].x, acc[7].x); acc[7].y = fmaf(wb.w, xv[u].y, acc[7].y);
        }
    }

    // ---- BN1 stats: sum over 256 batch elems (128 threads x 2) per node ------
#pragma unroll
    for (int j = 0; j < NPT; j++) {
        float s  = acc[j].x + acc[j].y;
        float s2 = acc[j].x * acc[j].x + acc[j].y * acc[j].y;
#pragma unroll
        for (int o = 16; o > 0; o >>= 1) {
            s  += __shfl_xor_sync(0xffffffffu, s,  o);
            s2 += __shfl_xor_sync(0xffffffffu, s2, o);
        }
        if (lane == 0) { rsum[half][hw][j] = s; rsq[half][hw][j] = s2; }
    }
    __syncthreads();
    if (htid < NPT) {
        float s = 0.f, s2 = 0.f;
#pragma unroll
        for (int w = 0; w < 4; w++) { s += rsum[half][w][htid]; s2 += rsq[half][w][htid]; }
        const float m   = s * (1.f / B);
        const float var = s2 * (1.f / B) - m * m;
        smean[half][htid] = m;
        srstd[half][htid] = rsqrtf(var + EPS);
    }
    __syncthreads();

    // ---- BN1 + LeakyReLU + Layer 2 dot ---------------------------------------
    float z0 = 0.f, z1 = 0.f;
#pragma unroll
    for (int j = 0; j < NPT; j++) {
        const float m = smean[half][j], r = srstd[half][j], w = sw2[half][j];
        float v0 = (acc[j].x - m) * r;  v0 = (v0 > 0.f) ? v0 : SLOPE * v0;
        float v1 = (acc[j].y - m) * r;  v1 = (v1 > 0.f) ? v1 : SLOPE * v1;
        z0 = fmaf(w, v0, z0);
        z1 = fmaf(w, v1, z1);
    }

    // ---- BN2 stats over 256 batch values -------------------------------------
    {
        float s = z0 + z1, s2 = z0 * z0 + z1 * z1;
#pragma unroll
        for (int o = 16; o > 0; o >>= 1) {
            s  += __shfl_xor_sync(0xffffffffu, s,  o);
            s2 += __shfl_xor_sync(0xffffffffu, s2, o);
        }
        if (lane == 0) { rsum[half][hw][NPT] = s; rsq[half][hw][NPT] = s2; }
    }
    __syncthreads();
    if (htid == 0) {
        float s = 0.f, s2 = 0.f;
#pragma unroll
        for (int w = 0; w < 4; w++) { s += rsum[half][w][NPT]; s2 += rsq[half][w][NPT]; }
        const float m   = s * (1.f / B);
        const float var = s2 * (1.f / B) - m * m;
        zmean[half] = m;
        zrstd[half] = rsqrtf(var + EPS);
    }
    __syncthreads();

    const float m = zmean[half], r = zrstd[half];
    float v0 = (z0 - m) * r;  v0 = (v0 > 0.f) ? v0 : SLOPE * v0;
    float v1 = (z1 - m) * r;  v1 = (v1 > 0.f) ? v1 : SLOPE * v1;
    out[(size_t)(boff)     * NTF + t] = v0;
    out[(size_t)(boff + 1) * NTF + t] = v1;
}

// ---------------------------------------------------------------------------
extern "C" void kernel_launch(void* const* d_in, const int* in_sizes, int n_in,
                              void* d_out, int out_size) {
    const float* x       = (const float*)d_in[0];
    const float* w1      = (const float*)d_in[1];
    const int*   in_idx1 = (const int*)  d_in[2];
    const float* w2      = (const float*)d_in[4];
    float*       out     = (float*)d_out;

    dim3 tb(32, 8);
    dim3 tg(G / 32, B / 32);           // 625 x 8, exact
    transpose_kernel<<<tg, tb>>>(x);
    fused_encoder_kernel<<<NTF / 2, 256>>>(w1, in_idx1, w2, out);
}

// round 3
// speedup vs baseline: 1.2931x; 1.0992x over previous
#include <cuda_runtime.h>
#include <cuda_bf16.h>

// Problem constants (fixed by the dataset)
#define B    256
#define G    20000
#define NTF  1024
#define NPT  8     // nodes per TF
#define GPT  64    // genes per TF
#define EPS  1e-5f
#define SLOPE 0.01f

// Scratch: x transposed to [G, B] for coalesced gene-row gathers. 20.48 MB.
__device__ float g_xT[(size_t)G * B];

// ---------------------------------------------------------------------------
// Kernel 1: transpose x [B, G] -> xT [G, B].  G = 625 * 32 exactly.
// ---------------------------------------------------------------------------
__global__ void __launch_bounds__(256) transpose_kernel(const float* __restrict__ x) {
    __shared__ float tile[32][33];
    const int g0 = blockIdx.x * 32;
    const int b0 = blockIdx.y * 32;
    const int tx = threadIdx.x;      // 0..31
    const int ty = threadIdx.y;      // 0..7

#pragma unroll
    for (int i = 0; i < 32; i += 8)
        tile[ty + i][tx] = x[(size_t)(b0 + ty + i) * G + (g0 + tx)];
    __syncthreads();
#pragma unroll
    for (int i = 0; i < 32; i += 8)
        g_xT[(size_t)(g0 + ty + i) * B + (b0 + tx)] = tile[tx][ty + i];
}

// ---------------------------------------------------------------------------
// Kernel 2: fused encoder. One 128-thread block per TF (grid = 1024).
//   Each thread owns 2 batch elements (float2).
//   layer1 -> BN1 -> LeakyReLU -> layer2 -> BN2 -> LeakyReLU -> out.
// 10 blocks/SM target for latency hiding of the random L2-hit gathers.
// ---------------------------------------------------------------------------
__global__ void __launch_bounds__(128, 10) fused_encoder_kernel(
    const float* __restrict__ w1,
    const int*   __restrict__ in_idx1,
    const float* __restrict__ w2,
    float*       __restrict__ out)
{
    const int tid  = threadIdx.x;     // 0..127
    const int wrp  = tid >> 5;        // 0..3
    const int lane = tid & 31;
    const int t    = blockIdx.x;

    __shared__ float sw1t[NPT * GPT];     // transposed: [g*8 + j]
    __shared__ int   sg[GPT];             // gene offsets pre-scaled by B
    __shared__ float sw2[NPT];
    __shared__ float rsum[4][NPT + 2];    // per-warp partials ([8] = z slot)
    __shared__ float rsq [4][NPT + 2];
    __shared__ float smean[NPT], srstd[NPT];
    __shared__ float zmean, zrstd;

    // ---- Stage weights (transposed to [gene][node]) + gene indices -----------
#pragma unroll
    for (int i = tid; i < NPT * GPT; i += 128) {
        const int j = i >> 6;          // node
        const int g = i & 63;          // gene slot
        sw1t[g * NPT + j] = w1[t * (NPT * GPT) + i];
    }
    if (tid < GPT) sg[tid]  = in_idx1[t * (NPT * GPT) + tid] * B;
    if (tid < NPT) sw2[tid] = w2[t * NPT + tid];
    __syncthreads();

    // ---- Layer 1: acc[j] (float2 over 2 batch elems) -------------------------
    float2 acc[NPT];
#pragma unroll
    for (int j = 0; j < NPT; j++) acc[j] = make_float2(0.f, 0.f);

    const int boff = 2 * tid;
#pragma unroll
    for (int g0 = 0; g0 < GPT; g0 += 4) {
        float2 xv[4];
#pragma unroll
        for (int u = 0; u < 4; u++)
            xv[u] = *(const float2*)&g_xT[sg[g0 + u] + boff];
#pragma unroll
        for (int u = 0; u < 4; u++) {
            const float4 wa = *(const float4*)&sw1t[(g0 + u) * NPT];
            const float4 wb = *(const float4*)&sw1t[(g0 + u) * NPT + 4];
            acc[0].x = fmaf(wa.x, xv[u].x, acc[0].x); acc[0].y = fmaf(wa.x, xv[u].y, acc[0].y);
            acc[1].x = fmaf(wa.y, xv[u].x, acc[1].x); acc[1].y = fmaf(wa.y, xv[u].y, acc[1].y);
            acc[2].x = fmaf(wa.z, xv[u].x, acc[2].x); acc[2].y = fmaf(wa.z, xv[u].y, acc[2].y);
            acc[3].x = fmaf(wa.w, xv[u].x, acc[3].x); acc[3].y = fmaf(wa.w, xv[u].y, acc[3].y);
            acc[4].x = fmaf(wb.x, xv[u].x, acc[4].x); acc[4].y = fmaf(wb.x, xv[u].y, acc[4].y);
            acc[5].x = fmaf(wb.y, xv[u].x, acc[5].x); acc[5].y = fmaf(wb.y, xv[u].y, acc[5].y);
            acc[6].x = fmaf(wb.z, xv[u].x, acc[6].x); acc[6].y = fmaf(wb.z, xv[u].y, acc[6].y);
            acc[7].x = fmaf(wb.w, xv[u].x, acc[7].x); acc[7].y = fmaf(wb.w, xv[u].y, acc[7].y);
        }
    }

    // ---- BN1 stats: sum over 256 batch elems (128 threads x 2) per node ------
#pragma unroll
    for (int j = 0; j < NPT; j++) {
        float s  = acc[j].x + acc[j].y;
        float s2 = acc[j].x * acc[j].x + acc[j].y * acc[j].y;
#pragma unroll
        for (int o = 16; o > 0; o >>= 1) {
            s  += __shfl_xor_sync(0xffffffffu, s,  o);
            s2 += __shfl_xor_sync(0xffffffffu, s2, o);
        }
        if (lane == 0) { rsum[wrp][j] = s; rsq[wrp][j] = s2; }
    }
    __syncthreads();
    if (tid < NPT) {
        float s = 0.f, s2 = 0.f;
#pragma unroll
        for (int w = 0; w < 4; w++) { s += rsum[w][tid]; s2 += rsq[w][tid]; }
        const float m   = s * (1.f / B);
        const float var = s2 * (1.f / B) - m * m;
        smean[tid] = m;
        srstd[tid] = rsqrtf(var + EPS);
    }
    __syncthreads();

    // ---- BN1 + LeakyReLU + Layer 2 dot ---------------------------------------
    float z0 = 0.f, z1 = 0.f;
#pragma unroll
    for (int j = 0; j < NPT; j++) {
        const float m = smean[j], r = srstd[j], w = sw2[j];
        float v0 = (acc[j].x - m) * r;  v0 = (v0 > 0.f) ? v0 : SLOPE * v0;
        float v1 = (acc[j].y - m) * r;  v1 = (v1 > 0.f) ? v1 : SLOPE * v1;
        z0 = fmaf(w, v0, z0);
        z1 = fmaf(w, v1, z1);
    }

    // ---- BN2 stats over 256 batch values -------------------------------------
    {
        float s = z0 + z1, s2 = z0 * z0 + z1 * z1;
#pragma unroll
        for (int o = 16; o > 0; o >>= 1) {
            s  += __shfl_xor_sync(0xffffffffu, s,  o);
            s2 += __shfl_xor_sync(0xffffffffu, s2, o);
        }
        if (lane == 0) { rsum[wrp][NPT] = s; rsq[wrp][NPT] = s2; }
    }
    __syncthreads();
    if (tid == 0) {
        float s = 0.f, s2 = 0.f;
#pragma unroll
        for (int w = 0; w < 4; w++) { s += rsum[w][NPT]; s2 += rsq[w][NPT]; }
        const float m   = s * (1.f / B);
        const float var = s2 * (1.f / B) - m * m;
        zmean = m;
        zrstd = rsqrtf(var + EPS);
    }
    __syncthreads();

    const float m = zmean, r = zrstd;
    float v0 = (z0 - m) * r;  v0 = (v0 > 0.f) ? v0 : SLOPE * v0;
    float v1 = (z1 - m) * r;  v1 = (v1 > 0.f) ? v1 : SLOPE * v1;
    out[(size_t)(boff)     * NTF + t] = v0;
    out[(size_t)(boff + 1) * NTF + t] = v1;
}

// ---------------------------------------------------------------------------
extern "C" void kernel_launch(void* const* d_in, const int* in_sizes, int n_in,
                              void* d_out, int out_size) {
    const float* x       = (const float*)d_in[0];
    const float* w1      = (const float*)d_in[1];
    const int*   in_idx1 = (const int*)  d_in[2];
    const float* w2      = (const float*)d_in[4];
    float*       out     = (float*)d_out;

    dim3 tb(32, 8);
    dim3 tg(G / 32, B / 32);           // 625 x 8, exact
    transpose_kernel<<<tg, tb>>>(x);
    fused_encoder_kernel<<<NTF, 128>>>(w1, in_idx1, w2, out);
}